// round 15
// baseline (speedup 1.0000x reference)
#include <cuda_runtime.h>
#include <math_constants.h>

#define BB 4
#define VV 4096
#define FF 64
#define SS 4
#define KN 39            // neighbours kept (K_NEIGHBOURS=40 includes self)
#define OUTF 64
#define QT 4             // queries per block
#define TPB 512          // QT x 128 threads
#define BND_MAX 64
#define NB 512           // histogram bins
#define KBASE 760        // (u>>20) offset: covers biased exponents 95..158

// Scratch (device globals; no allocation allowed)
__device__ float g_coords[BB * VV * 4];     // (b, v, 4) — float4-aligned rows
__device__ float g_feats[BB * VV * FF];     // (b, v, 64)

// ---------------------------------------------------------------------------
// Kernel 1: coords = x@Ws + bs, feats = x@Wf + bf  (4 vertices per block)
// ---------------------------------------------------------------------------
__global__ void __launch_bounds__(256) prep_kernel(
    const float* __restrict__ x,
    const float* __restrict__ Wf, const float* __restrict__ bf,
    const float* __restrict__ Ws, const float* __restrict__ bs)
{
    const int g   = threadIdx.x >> 6;          // vertex group 0..3
    const int f   = threadIdx.x & 63;
    const int vtx = blockIdx.x * 4 + g;
    __shared__ float sx[4][FF];
    sx[g][f] = x[vtx * FF + f];
    __syncthreads();

    float acc = bf[f];
#pragma unroll
    for (int k = 0; k < FF; ++k)
        acc = fmaf(sx[g][k], Wf[k * FF + f], acc);
    g_feats[vtx * FF + f] = acc;

    if (f < SS) {
        float c = bs[f];
#pragma unroll
        for (int k = 0; k < FF; ++k)
            c = fmaf(sx[g][k], Ws[k * SS + f], c);
        g_coords[vtx * 4 + f] = c;
    }
}

__device__ __forceinline__ int d2_key(unsigned u)
{
    int p = (int)(u >> 20) - KBASE;
    p = max(p, 0);
    return min(p, NB - 1);
}

// Named barrier for one 128-thread quarter (query q uses id q+1).
__device__ __forceinline__ void barq(int q)
{
    asm volatile("bar.sync %0, 128;" :: "r"(q + 1) : "memory");
}

// Dynamic shared-memory layout (~91 KB -> dynamic smem required)
struct GravSmem {
    float4 d2v[QT][VV / 4];                    // 64 KB
    unsigned hist[QT][NB];                     // 8 KB
    float cat[QT][192];                        // [xq | max | mean]
    int   nidx[QT][KN + 1];
    float nd2[QT][KN + 1];
    float nw[QT][KN + 1];
    float mx2[QT][64], sm2[QT][64];
    float part[8][QT][64];                     // GEMM partials [kseg][q][o]
    unsigned long long bnd[QT][BND_MAX];
    unsigned long long red[QT][4];
    unsigned long long win[QT];
    int cdef[QT], cbnd[QT], bkey[QT], cc[QT];
    int wsc[QT][4];
};

// ---------------------------------------------------------------------------
// Kernel 2: FOUR queries per block. Shared coord loads in pass 1; shared Wo
// lines in the output GEMM. Per-query select/aggregate runs in each
// 128-thread quarter, synchronized with named barriers.
// ---------------------------------------------------------------------------
__global__ void __launch_bounds__(TPB, 2) grav_kernel(
    const float* __restrict__ x,
    const float* __restrict__ Wo, const float* __restrict__ bo,
    float* __restrict__ out)
{
    extern __shared__ GravSmem sm[];
    GravSmem& S = sm[0];

    const int v0   = blockIdx.x * QT;  // first query vertex of this block
    const int b    = blockIdx.y;       // batch
    const int tid  = threadIdx.x;
    const int lane = tid & 31;
    const int q    = tid >> 7;         // query quarter: 0..3
    const int wt   = tid & 127;        // thread index within quarter
    const int base = b * VV;

    const float4* cb = reinterpret_cast<const float4*>(g_coords) + base;
    const float4 cq0 = cb[v0];
    const float4 cq1 = cb[v0 + 1];
    const float4 cq2 = cb[v0 + 2];
    const float4 cq3 = cb[v0 + 3];
    float* s_d2q = reinterpret_cast<float*>(S.d2v[q]);

    if (tid < QT * FF)
        S.cat[tid >> 6][tid & 63] =
            x[(base + v0 + (tid >> 6)) * FF + (tid & 63)];
    reinterpret_cast<uint4*>(&S.hist[0][0])[tid] = make_uint4(0u, 0u, 0u, 0u);
    if (tid < QT) { S.cdef[tid] = 0; S.cbnd[tid] = 0; }
    __syncthreads();

    // ---- Pass 1: one coord load -> four distances + four histogram bumps.
    //      Self d2 == 0 exactly (bin 0); patched out afterwards. ----
    {
        float* d0 = reinterpret_cast<float*>(S.d2v[0]);
        float* d1 = reinterpret_cast<float*>(S.d2v[1]);
        float* d2p = reinterpret_cast<float*>(S.d2v[2]);
        float* d3 = reinterpret_cast<float*>(S.d2v[3]);
#pragma unroll 2
        for (int i = tid; i < VV; i += TPB) {
            float4 cu = cb[i];
            float ax = cq0.x - cu.x, ay = cq0.y - cu.y;
            float az = cq0.z - cu.z, aw = cq0.w - cu.w;
            float e0 = fmaf(ax, ax, fmaf(ay, ay, fmaf(az, az, aw * aw)));
            ax = cq1.x - cu.x; ay = cq1.y - cu.y;
            az = cq1.z - cu.z; aw = cq1.w - cu.w;
            float e1 = fmaf(ax, ax, fmaf(ay, ay, fmaf(az, az, aw * aw)));
            ax = cq2.x - cu.x; ay = cq2.y - cu.y;
            az = cq2.z - cu.z; aw = cq2.w - cu.w;
            float e2 = fmaf(ax, ax, fmaf(ay, ay, fmaf(az, az, aw * aw)));
            ax = cq3.x - cu.x; ay = cq3.y - cu.y;
            az = cq3.z - cu.z; aw = cq3.w - cu.w;
            float e3 = fmaf(ax, ax, fmaf(ay, ay, fmaf(az, az, aw * aw)));
            d0[i] = e0; d1[i] = e1; d2p[i] = e2; d3[i] = e3;
            atomicAdd(&S.hist[0][d2_key(__float_as_uint(e0))], 1u);
            atomicAdd(&S.hist[1][d2_key(__float_as_uint(e1))], 1u);
            atomicAdd(&S.hist[2][d2_key(__float_as_uint(e2))], 1u);
            atomicAdd(&S.hist[3][d2_key(__float_as_uint(e3))], 1u);
        }
    }
    __syncthreads();
    if (tid < QT) {
        S.hist[tid][0]      -= 1u;              // remove self (d2=0 -> bin 0)
        S.hist[tid][NB - 1] += 1u;              // park self in top bin
        reinterpret_cast<float*>(S.d2v[tid])[v0 + tid] = CUDART_INF_F;
    }
    __syncthreads();

    // ---- Parallel scan, all four histograms concurrently ----
    {
        uint4 a = reinterpret_cast<const uint4*>(&S.hist[q][0])[wt];
        int h0 = (int)a.x, h1 = (int)a.y, h2 = (int)a.z, h3 = (int)a.w;
        int lsum = h0 + h1 + h2 + h3;
        int incl = lsum;
#pragma unroll
        for (int o = 1; o < 32; o <<= 1) {
            int n = __shfl_up_sync(0xffffffffu, incl, o);
            if (lane >= o) incl += n;
        }
        if (lane == 31) S.wsc[q][wt >> 5] = incl;
        __syncthreads();
        int wprefix = 0;
        const int wid = wt >> 5;
        if (wid > 0) wprefix += S.wsc[q][0];
        if (wid > 1) wprefix += S.wsc[q][1];
        if (wid > 2) wprefix += S.wsc[q][2];
        int excl = wprefix + incl - lsum;       // count before bin wt*4
        if (excl < KN && excl + lsum >= KN) {
            int cum = excl, bin = 4 * wt;
            if (cum + h0 < KN) { cum += h0; ++bin;
                if (cum + h1 < KN) { cum += h1; ++bin;
                    if (cum + h2 < KN) { cum += h2; ++bin; } } }
            S.bkey[q] = bin; S.cc[q] = cum;
        }
        __syncthreads();
    }
    const int bkey = S.bkey[q];
    const int c = S.cc[q];                      // definite count (< 39)
    const int vq = v0 + q;
    const unsigned lo_u = (bkey == 0) ? 0u
                        : ((unsigned)(bkey + KBASE) << 20);
    const unsigned hi_u = (bkey == NB - 1) ? 0xFFFFFFFFu
                        : ((unsigned)(bkey + 1 + KBASE) << 20);

    // ---- Gather (quarter q sweeps its own d2 array; 2 compares/cand) ----
    for (int it = 0; it < VV / 4 / 128; ++it) {
        int i4 = it * 128 + wt;
        float4 d4 = S.d2v[q][i4];
        int ib = i4 * 4;
#pragma unroll
        for (int e = 0; e < 4; ++e) {
            float dv = (e == 0) ? d4.x : (e == 1) ? d4.y : (e == 2) ? d4.z : d4.w;
            unsigned u = __float_as_uint(dv);
            if (u < hi_u) {
                if (u < lo_u) {
                    int pos = atomicAdd(&S.cdef[q], 1);
                    S.nidx[q][pos] = ib + e;
                    S.nd2[q][pos] = dv;
                } else if (ib + e != vq) {
                    int pos = atomicAdd(&S.cbnd[q], 1);
                    if (pos < BND_MAX)
                        S.bnd[q][pos] = ((unsigned long long)u << 32)
                                        | (unsigned)(ib + e);
                }
            }
        }
    }
    barq(q);

    const int m = S.cbnd[q];
    const int r = KN - c;                       // boundary picks needed (>=1)

    if (m <= BND_MAX) {
        // Extract r smallest by (d2, idx) from the small boundary list.
        for (int j = 0; j < r; ++j) {
            unsigned long long lk = (wt < m) ? S.bnd[q][wt]
                                             : 0xFFFFFFFFFFFFFFFFULL;
#pragma unroll
            for (int o = 16; o > 0; o >>= 1) {
                unsigned long long oth = __shfl_down_sync(0xffffffffu, lk, o);
                lk = (oth < lk) ? oth : lk;
            }
            if (lane == 0) S.red[q][wt >> 5] = lk;
            barq(q);
            if (wt == 0) {
                unsigned long long w0 = S.red[q][0];
                if (S.red[q][1] < w0) w0 = S.red[q][1];
                if (S.red[q][2] < w0) w0 = S.red[q][2];
                if (S.red[q][3] < w0) w0 = S.red[q][3];
                S.win[q] = w0;
                S.nidx[q][c + j] = (int)(w0 & 0xFFFFFFFFULL);
                S.nd2[q][c + j]  = __uint_as_float((unsigned)(w0 >> 32));
            }
            barq(q);
            if (wt < m && S.bnd[q][wt] == S.win[q])
                S.bnd[q][wt] = 0xFFFFFFFFFFFFFFFFULL;
            barq(q);
        }
    } else {
        // Degenerate fallback (massive tie bin): exact extraction over d2.
        for (int j = 0; j < r; ++j) {
            unsigned long long lk = 0xFFFFFFFFFFFFFFFFULL;
            for (int i = wt; i < VV; i += 128) {
                unsigned u = __float_as_uint(s_d2q[i]);
                if (u >= lo_u && u < hi_u && i != vq) {
                    unsigned long long key =
                        ((unsigned long long)u << 32) | (unsigned)i;
                    if (key < lk) lk = key;
                }
            }
#pragma unroll
            for (int o = 16; o > 0; o >>= 1) {
                unsigned long long oth = __shfl_down_sync(0xffffffffu, lk, o);
                lk = (oth < lk) ? oth : lk;
            }
            if (lane == 0) S.red[q][wt >> 5] = lk;
            barq(q);
            if (wt == 0) {
                unsigned long long w0 = S.red[q][0];
                if (S.red[q][1] < w0) w0 = S.red[q][1];
                if (S.red[q][2] < w0) w0 = S.red[q][2];
                if (S.red[q][3] < w0) w0 = S.red[q][3];
                int widx = (int)(w0 & 0xFFFFFFFFULL);
                S.nidx[q][c + j] = widx;
                S.nd2[q][c + j]  = __uint_as_float((unsigned)(w0 >> 32));
                s_d2q[widx] = __uint_as_float(0xFFFFFFFFu); // consumed
            }
            barq(q);
        }
    }

    // ---- Weights ----
    if (wt < KN)
        S.nw[q][wt] = expf(-10.0f * fabsf(S.nd2[q][wt]));
    barq(q);

    // ---- Weighted aggregation: max + mean over 39 (per query quarter) ----
    {
        const float* fb = g_feats + (size_t)base * FF;
        const int f = wt & 63;
        const int hj = wt >> 6;
        float mx = -CUDART_INF_F;
        float sm2 = 0.0f;
        if (hj) {
#pragma unroll 4
            for (int j = 20; j < KN; ++j) {
                float val = fb[S.nidx[q][j] * FF + f] * S.nw[q][j];
                mx = fmaxf(mx, val);
                sm2 += val;
            }
            S.mx2[q][f] = mx; S.sm2[q][f] = sm2;
        } else {
#pragma unroll 4
            for (int j = 0; j < 20; ++j) {
                float val = fb[S.nidx[q][j] * FF + f] * S.nw[q][j];
                mx = fmaxf(mx, val);
                sm2 += val;
            }
        }
        barq(q);
        if (!hj) {
            mx = fmaxf(mx, S.mx2[q][f]);
            sm2 += S.sm2[q][f];
            S.cat[q][FF + f]     = mx;
            S.cat[q][2 * FF + f] = sm2 * (1.0f / KN);
        }
    }
    __syncthreads();

    // ---- Output GEMM, Wo shared across all four queries:
    //      each Wo element is loaded ONCE per block and FMA'd into four
    //      accumulators. 512 thr = 64 outputs x 8 k-segments (24 k each). ----
    {
        const int o = tid & 63;
        const int kseg = tid >> 6;              // 0..7
        const int k0 = kseg * 24;
        float a0 = 0.0f, a1 = 0.0f, a2 = 0.0f, a3 = 0.0f;
#pragma unroll
        for (int kk = 0; kk < 24; ++kk) {
            int k = k0 + kk;
            float w = Wo[k * OUTF + o];
            a0 = fmaf(S.cat[0][k], w, a0);
            a1 = fmaf(S.cat[1][k], w, a1);
            a2 = fmaf(S.cat[2][k], w, a2);
            a3 = fmaf(S.cat[3][k], w, a3);
        }
        S.part[kseg][0][o] = a0;
        S.part[kseg][1][o] = a1;
        S.part[kseg][2][o] = a2;
        S.part[kseg][3][o] = a3;
        __syncthreads();
        if (tid < QT * 64) {
            int qq = tid >> 6, oo = tid & 63;
            float acc = bo[oo];
#pragma unroll
            for (int s = 0; s < 8; ++s) acc += S.part[s][qq][oo];
            out[(base + v0 + qq) * OUTF + oo] = tanhf(acc);
        }
    }
}

// ---------------------------------------------------------------------------
extern "C" void kernel_launch(void* const* d_in, const int* in_sizes, int n_in,
                              void* d_out, int out_size)
{
    const float* x  = (const float*)d_in[0];
    const float* Wf = (const float*)d_in[1];
    const float* bf = (const float*)d_in[2];
    const float* Ws = (const float*)d_in[3];
    const float* bs = (const float*)d_in[4];
    const float* Wo = (const float*)d_in[5];
    const float* bo = (const float*)d_in[6];
    float* out = (float*)d_out;

    cudaFuncSetAttribute(grav_kernel,
                         cudaFuncAttributeMaxDynamicSharedMemorySize,
                         (int)sizeof(GravSmem));

    prep_kernel<<<BB * VV / 4, 256>>>(x, Wf, bf, Ws, bs);

    dim3 grid(VV / QT, BB);
    grav_kernel<<<grid, TPB, sizeof(GravSmem)>>>(x, Wo, bo, out);
}

// round 16
// speedup vs baseline: 1.0652x; 1.0652x over previous
#include <cuda_runtime.h>
#include <math_constants.h>

#define BB 4
#define VV 4096
#define FF 64
#define SS 4
#define KN 39            // neighbours kept (K_NEIGHBOURS=40 includes self)
#define OUTF 64
#define QT 4             // queries per block
#define TPB 512          // QT x 128 threads
#define BND_MAX 64
#define NB 512           // histogram bins
#define KBASE 760        // (u>>20) offset: covers biased exponents 95..158

// Scratch (device globals; no allocation allowed)
__device__ float g_coords[BB * VV * 4];     // (b, v, 4) — float4-aligned rows
__device__ float g_feats[BB * VV * FF];     // (b, v, 64)

// ---------------------------------------------------------------------------
// Kernel 1: coords = x@Ws + bs, feats = x@Wf + bf  (4 vertices per block)
// ---------------------------------------------------------------------------
__global__ void __launch_bounds__(256) prep_kernel(
    const float* __restrict__ x,
    const float* __restrict__ Wf, const float* __restrict__ bf,
    const float* __restrict__ Ws, const float* __restrict__ bs)
{
    const int g   = threadIdx.x >> 6;          // vertex group 0..3
    const int f   = threadIdx.x & 63;
    const int vtx = blockIdx.x * 4 + g;
    __shared__ float sx[4][FF];
    sx[g][f] = x[vtx * FF + f];
    __syncthreads();

    float acc = bf[f];
#pragma unroll
    for (int k = 0; k < FF; ++k)
        acc = fmaf(sx[g][k], Wf[k * FF + f], acc);
    g_feats[vtx * FF + f] = acc;

    if (f < SS) {
        float c = bs[f];
#pragma unroll
        for (int k = 0; k < FF; ++k)
            c = fmaf(sx[g][k], Ws[k * SS + f], c);
        g_coords[vtx * 4 + f] = c;
    }
}

__device__ __forceinline__ int d2_key(unsigned u)
{
    int p = (int)(u >> 20) - KBASE;
    p = max(p, 0);
    return min(p, NB - 1);
}

// Exact same FMA expression as pass 1 -> bit-identical d2 on recompute.
__device__ __forceinline__ float dist2(float4 cq, float4 cu)
{
    float ax = cq.x - cu.x, ay = cq.y - cu.y;
    float az = cq.z - cu.z, aw = cq.w - cu.w;
    return fmaf(ax, ax, fmaf(ay, ay, fmaf(az, az, aw * aw)));
}

// Named barrier for one 128-thread quarter (query q uses id q+1).
__device__ __forceinline__ void barq(int q)
{
    asm volatile("bar.sync %0, 128;" :: "r"(q + 1) : "memory");
}

// Dynamic shared-memory layout (~58 KB -> 3 blocks/SM)
struct GravSmem {
    unsigned short pref[QT][VV];               // 32 KB: d2 bits >> 16
    unsigned hist[QT][NB];                     // 8 KB
    float cat[QT][192];                        // [xq | max | mean]
    int   nidx[QT][KN + 1];
    float nd2[QT][KN + 1];
    float nw[QT][KN + 1];
    float mx2[QT][64], sm2[QT][64];
    float part[8][QT][64];                     // GEMM partials [kseg][q][o]
    unsigned long long bnd[QT][BND_MAX];
    unsigned long long red[QT][4];
    unsigned long long win[QT];
    int cdef[QT], cbnd[QT], bkey[QT], cc[QT];
    int wsc[QT][4];
};

// ---------------------------------------------------------------------------
// Kernel 2: FOUR queries per block. Shared coord loads; 16-bit d2 prefixes
// in smem; exact d2 recomputed only for the ~45 gathered candidates.
// ---------------------------------------------------------------------------
__global__ void __launch_bounds__(TPB, 3) grav_kernel(
    const float* __restrict__ x,
    const float* __restrict__ Wo, const float* __restrict__ bo,
    float* __restrict__ out)
{
    extern __shared__ GravSmem sm[];
    GravSmem& S = sm[0];

    const int v0   = blockIdx.x * QT;  // first query vertex of this block
    const int b    = blockIdx.y;       // batch
    const int tid  = threadIdx.x;
    const int lane = tid & 31;
    const int q    = tid >> 7;         // query quarter: 0..3
    const int wt   = tid & 127;        // thread index within quarter
    const int base = b * VV;

    const float4* cb = reinterpret_cast<const float4*>(g_coords) + base;
    const float4 cq0 = cb[v0];
    const float4 cq1 = cb[v0 + 1];
    const float4 cq2 = cb[v0 + 2];
    const float4 cq3 = cb[v0 + 3];

    if (tid < QT * FF)
        S.cat[tid >> 6][tid & 63] =
            x[(base + v0 + (tid >> 6)) * FF + (tid & 63)];
    reinterpret_cast<uint4*>(&S.hist[0][0])[tid] = make_uint4(0u, 0u, 0u, 0u);
    if (tid < QT) { S.cdef[tid] = 0; S.cbnd[tid] = 0; }
    __syncthreads();

    // ---- Pass 1: one coord load -> four distances; store 16-bit prefixes
    //      + four histogram bumps. Self d2 == 0 (bin 0); patched after. ----
#pragma unroll 2
    for (int i = tid; i < VV; i += TPB) {
        float4 cu = cb[i];
        float e0 = dist2(cq0, cu);
        float e1 = dist2(cq1, cu);
        float e2 = dist2(cq2, cu);
        float e3 = dist2(cq3, cu);
        unsigned u0 = __float_as_uint(e0);
        unsigned u1 = __float_as_uint(e1);
        unsigned u2 = __float_as_uint(e2);
        unsigned u3 = __float_as_uint(e3);
        S.pref[0][i] = (unsigned short)(u0 >> 16);
        S.pref[1][i] = (unsigned short)(u1 >> 16);
        S.pref[2][i] = (unsigned short)(u2 >> 16);
        S.pref[3][i] = (unsigned short)(u3 >> 16);
        atomicAdd(&S.hist[0][d2_key(u0)], 1u);
        atomicAdd(&S.hist[1][d2_key(u1)], 1u);
        atomicAdd(&S.hist[2][d2_key(u2)], 1u);
        atomicAdd(&S.hist[3][d2_key(u3)], 1u);
    }
    __syncthreads();
    if (tid < QT) {
        S.hist[tid][0]      -= 1u;              // remove self (d2=0 -> bin 0)
        S.hist[tid][NB - 1] += 1u;              // park self in top bin
        S.pref[tid][v0 + tid] = 0xFFFFu;        // sentinel: never gathered
    }
    __syncthreads();

    // ---- Parallel scan, all four histograms concurrently ----
    {
        uint4 a = reinterpret_cast<const uint4*>(&S.hist[q][0])[wt];
        int h0 = (int)a.x, h1 = (int)a.y, h2 = (int)a.z, h3 = (int)a.w;
        int lsum = h0 + h1 + h2 + h3;
        int incl = lsum;
#pragma unroll
        for (int o = 1; o < 32; o <<= 1) {
            int n = __shfl_up_sync(0xffffffffu, incl, o);
            if (lane >= o) incl += n;
        }
        if (lane == 31) S.wsc[q][wt >> 5] = incl;
        __syncthreads();
        int wprefix = 0;
        const int wid = wt >> 5;
        if (wid > 0) wprefix += S.wsc[q][0];
        if (wid > 1) wprefix += S.wsc[q][1];
        if (wid > 2) wprefix += S.wsc[q][2];
        int excl = wprefix + incl - lsum;       // count before bin wt*4
        if (excl < KN && excl + lsum >= KN) {
            int cum = excl, bin = 4 * wt;
            if (cum + h0 < KN) { cum += h0; ++bin;
                if (cum + h1 < KN) { cum += h1; ++bin;
                    if (cum + h2 < KN) { cum += h2; ++bin; } } }
            S.bkey[q] = bin; S.cc[q] = cum;
        }
        __syncthreads();
    }
    const int bkey = S.bkey[q];
    const int c = S.cc[q];                      // definite count (< 39)
    const float4 cqm = (q == 0) ? cq0 : (q == 1) ? cq1 : (q == 2) ? cq2 : cq3;
    // 16-bit thresholds; bin bounds are multiples of 2^20, so exact.
    const unsigned lo16 = (bkey == 0) ? 0u
                        : ((unsigned)(bkey + KBASE) << 4);
    const unsigned hi16 = (bkey == NB - 1) ? 0xFFFFu
                        : ((unsigned)(bkey + 1 + KBASE) << 4);

    // ---- Gather: sweep own prefix array (uint4 = 8 candidates/iter);
    //      recompute exact d2 only for hits (~45 per query). ----
    for (int it = 0; it < VV / 8 / 128; ++it) {
        int i8 = it * 128 + wt;
        uint4 a = reinterpret_cast<const uint4*>(&S.pref[q][0])[i8];
        int ib = i8 * 8;
#pragma unroll
        for (int e = 0; e < 8; ++e) {
            unsigned word = (e < 2) ? a.x : (e < 4) ? a.y : (e < 6) ? a.z : a.w;
            unsigned p16 = (e & 1) ? (word >> 16) : (word & 0xFFFFu);
            if (p16 < hi16) {
                int i = ib + e;
                float dv = dist2(cqm, cb[i]);
                if (p16 < lo16) {
                    int pos = atomicAdd(&S.cdef[q], 1);
                    S.nidx[q][pos] = i;
                    S.nd2[q][pos] = dv;
                } else {
                    int pos = atomicAdd(&S.cbnd[q], 1);
                    if (pos < BND_MAX)
                        S.bnd[q][pos] =
                            ((unsigned long long)__float_as_uint(dv) << 32)
                            | (unsigned)i;
                }
            }
        }
    }
    barq(q);

    const int m = S.cbnd[q];
    const int r = KN - c;                       // boundary picks needed (>=1)

    if (m <= BND_MAX) {
        // Extract r smallest by (d2, idx) from the small boundary list.
        for (int j = 0; j < r; ++j) {
            unsigned long long lk = (wt < m) ? S.bnd[q][wt]
                                             : 0xFFFFFFFFFFFFFFFFULL;
#pragma unroll
            for (int o = 16; o > 0; o >>= 1) {
                unsigned long long oth = __shfl_down_sync(0xffffffffu, lk, o);
                lk = (oth < lk) ? oth : lk;
            }
            if (lane == 0) S.red[q][wt >> 5] = lk;
            barq(q);
            if (wt == 0) {
                unsigned long long w0 = S.red[q][0];
                if (S.red[q][1] < w0) w0 = S.red[q][1];
                if (S.red[q][2] < w0) w0 = S.red[q][2];
                if (S.red[q][3] < w0) w0 = S.red[q][3];
                S.win[q] = w0;
                S.nidx[q][c + j] = (int)(w0 & 0xFFFFFFFFULL);
                S.nd2[q][c + j]  = __uint_as_float((unsigned)(w0 >> 32));
            }
            barq(q);
            if (wt < m && S.bnd[q][wt] == S.win[q])
                S.bnd[q][wt] = 0xFFFFFFFFFFFFFFFFULL;
            barq(q);
        }
    } else {
        // Degenerate fallback (massive tie bin): exact extraction over
        // prefixes with recompute; consumed entries marked in pref.
        for (int j = 0; j < r; ++j) {
            unsigned long long lk = 0xFFFFFFFFFFFFFFFFULL;
            for (int i = wt; i < VV; i += 128) {
                unsigned p16 = S.pref[q][i];
                if (p16 >= lo16 && p16 < hi16) {
                    unsigned u = __float_as_uint(dist2(cqm, cb[i]));
                    unsigned long long key =
                        ((unsigned long long)u << 32) | (unsigned)i;
                    if (key < lk) lk = key;
                }
            }
#pragma unroll
            for (int o = 16; o > 0; o >>= 1) {
                unsigned long long oth = __shfl_down_sync(0xffffffffu, lk, o);
                lk = (oth < lk) ? oth : lk;
            }
            if (lane == 0) S.red[q][wt >> 5] = lk;
            barq(q);
            if (wt == 0) {
                unsigned long long w0 = S.red[q][0];
                if (S.red[q][1] < w0) w0 = S.red[q][1];
                if (S.red[q][2] < w0) w0 = S.red[q][2];
                if (S.red[q][3] < w0) w0 = S.red[q][3];
                int widx = (int)(w0 & 0xFFFFFFFFULL);
                S.nidx[q][c + j] = widx;
                S.nd2[q][c + j]  = __uint_as_float((unsigned)(w0 >> 32));
                S.pref[q][widx] = 0xFFFFu;      // consumed marker
            }
            barq(q);
        }
    }

    // ---- Weights ----
    if (wt < KN)
        S.nw[q][wt] = expf(-10.0f * fabsf(S.nd2[q][wt]));
    barq(q);

    // ---- Weighted aggregation: max + mean over 39 (per query quarter) ----
    {
        const float* fb = g_feats + (size_t)base * FF;
        const int f = wt & 63;
        const int hj = wt >> 6;
        float mx = -CUDART_INF_F;
        float sm2 = 0.0f;
        if (hj) {
#pragma unroll 4
            for (int j = 20; j < KN; ++j) {
                float val = fb[S.nidx[q][j] * FF + f] * S.nw[q][j];
                mx = fmaxf(mx, val);
                sm2 += val;
            }
            S.mx2[q][f] = mx; S.sm2[q][f] = sm2;
        } else {
#pragma unroll 4
            for (int j = 0; j < 20; ++j) {
                float val = fb[S.nidx[q][j] * FF + f] * S.nw[q][j];
                mx = fmaxf(mx, val);
                sm2 += val;
            }
        }
        barq(q);
        if (!hj) {
            mx = fmaxf(mx, S.mx2[q][f]);
            sm2 += S.sm2[q][f];
            S.cat[q][FF + f]     = mx;
            S.cat[q][2 * FF + f] = sm2 * (1.0f / KN);
        }
    }
    __syncthreads();

    // ---- Output GEMM, Wo shared across all four queries ----
    {
        const int o = tid & 63;
        const int kseg = tid >> 6;              // 0..7
        const int k0 = kseg * 24;
        float a0 = 0.0f, a1 = 0.0f, a2 = 0.0f, a3 = 0.0f;
#pragma unroll
        for (int kk = 0; kk < 24; ++kk) {
            int k = k0 + kk;
            float w = Wo[k * OUTF + o];
            a0 = fmaf(S.cat[0][k], w, a0);
            a1 = fmaf(S.cat[1][k], w, a1);
            a2 = fmaf(S.cat[2][k], w, a2);
            a3 = fmaf(S.cat[3][k], w, a3);
        }
        S.part[kseg][0][o] = a0;
        S.part[kseg][1][o] = a1;
        S.part[kseg][2][o] = a2;
        S.part[kseg][3][o] = a3;
        __syncthreads();
        if (tid < QT * 64) {
            int qq = tid >> 6, oo = tid & 63;
            float acc = bo[oo];
#pragma unroll
            for (int s = 0; s < 8; ++s) acc += S.part[s][qq][oo];
            out[(base + v0 + qq) * OUTF + oo] = tanhf(acc);
        }
    }
}

// ---------------------------------------------------------------------------
extern "C" void kernel_launch(void* const* d_in, const int* in_sizes, int n_in,
                              void* d_out, int out_size)
{
    const float* x  = (const float*)d_in[0];
    const float* Wf = (const float*)d_in[1];
    const float* bf = (const float*)d_in[2];
    const float* Ws = (const float*)d_in[3];
    const float* bs = (const float*)d_in[4];
    const float* Wo = (const float*)d_in[5];
    const float* bo = (const float*)d_in[6];
    float* out = (float*)d_out;

    cudaFuncSetAttribute(grav_kernel,
                         cudaFuncAttributeMaxDynamicSharedMemorySize,
                         (int)sizeof(GravSmem));

    prep_kernel<<<BB * VV / 4, 256>>>(x, Wf, bf, Ws, bs);

    dim3 grid(VV / QT, BB);
    grav_kernel<<<grid, TPB, sizeof(GravSmem)>>>(x, Wo, bo, out);
}

// round 17
// speedup vs baseline: 1.1814x; 1.1091x over previous
#include <cuda_runtime.h>
#include <math_constants.h>

#define BB 4
#define VV 4096
#define FF 64
#define SS 4
#define KN 39            // neighbours kept (K_NEIGHBOURS=40 includes self)
#define OUTF 64
#define QT 4             // queries per block
#define TPB 512          // QT x 128 threads
#define BND_MAX 64
#define NB 1024          // histogram bins
#define KBASE 1520       // (u>>19) offset: covers biased exponents 95..158

// Scratch (device globals; no allocation allowed)
__device__ float g_coords[BB * VV * 4];     // (b, v, 4) — float4-aligned rows
__device__ float g_feats[BB * VV * FF];     // (b, v, 64)

// ---------------------------------------------------------------------------
// Kernel 1: coords = x@Ws + bs, feats = x@Wf + bf  (4 vertices per block)
// ---------------------------------------------------------------------------
__global__ void __launch_bounds__(256) prep_kernel(
    const float* __restrict__ x,
    const float* __restrict__ Wf, const float* __restrict__ bf,
    const float* __restrict__ Ws, const float* __restrict__ bs)
{
    const int g   = threadIdx.x >> 6;          // vertex group 0..3
    const int f   = threadIdx.x & 63;
    const int vtx = blockIdx.x * 4 + g;
    __shared__ float sx[4][FF];
    sx[g][f] = x[vtx * FF + f];
    __syncthreads();

    float acc = bf[f];
#pragma unroll
    for (int k = 0; k < FF; ++k)
        acc = fmaf(sx[g][k], Wf[k * FF + f], acc);
    g_feats[vtx * FF + f] = acc;

    if (f < SS) {
        float c = bs[f];
#pragma unroll
        for (int k = 0; k < FF; ++k)
            c = fmaf(sx[g][k], Ws[k * SS + f], c);
        g_coords[vtx * 4 + f] = c;
    }
}

__device__ __forceinline__ int d2_key(unsigned u)
{
    int p = (int)(u >> 19) - KBASE;
    p = max(p, 0);
    return min(p, NB - 1);
}

// Exact same FMA expression as pass 1 -> bit-identical d2 on recompute.
__device__ __forceinline__ float dist2(float4 cq, float4 cu)
{
    float ax = cq.x - cu.x, ay = cq.y - cu.y;
    float az = cq.z - cu.z, aw = cq.w - cu.w;
    return fmaf(ax, ax, fmaf(ay, ay, fmaf(az, az, aw * aw)));
}

// Named barrier for one 128-thread quarter (query q uses id q+1).
__device__ __forceinline__ void barq(int q)
{
    asm volatile("bar.sync %0, 128;" :: "r"(q + 1) : "memory");
}

__device__ __forceinline__ unsigned long long ullmin2(
    unsigned long long a, unsigned long long b)
{
    return a < b ? a : b;
}

// Dynamic shared-memory layout (~67 KB -> 3 blocks/SM)
struct GravSmem {
    unsigned short pref[QT][VV];               // 32 KB: d2 bits >> 16
    unsigned hist[QT][NB];                     // 16 KB
    float cat[QT][192];                        // [xq | max | mean]
    int   nidx[QT][KN + 1];
    float nd2[QT][KN + 1];
    float nw[QT][KN + 1];
    float mx2[QT][64], sm2[QT][64];
    float part[8][QT][64];                     // GEMM partials [kseg][q][o]
    unsigned long long bnd[QT][BND_MAX];
    unsigned long long red[QT][4];
    unsigned long long win[QT];
    int cdef[QT], cbnd[QT], bkey[QT], cc[QT];
    int wsc[QT][4];
};

// ---------------------------------------------------------------------------
// Kernel 2: FOUR queries per block. Shared coord loads; 16-bit d2 prefixes
// in smem; exact d2 recomputed only for the ~45 gathered candidates;
// warp-local boundary extraction (no barriers) in the common case.
// ---------------------------------------------------------------------------
__global__ void __launch_bounds__(TPB, 3) grav_kernel(
    const float* __restrict__ x,
    const float* __restrict__ Wo, const float* __restrict__ bo,
    float* __restrict__ out)
{
    extern __shared__ GravSmem sm[];
    GravSmem& S = sm[0];

    const int v0   = blockIdx.x * QT;  // first query vertex of this block
    const int b    = blockIdx.y;       // batch
    const int tid  = threadIdx.x;
    const int lane = tid & 31;
    const int q    = tid >> 7;         // query quarter: 0..3
    const int wt   = tid & 127;        // thread index within quarter
    const int base = b * VV;

    const float4* cb = reinterpret_cast<const float4*>(g_coords) + base;
    const float4 cq0 = cb[v0];
    const float4 cq1 = cb[v0 + 1];
    const float4 cq2 = cb[v0 + 2];
    const float4 cq3 = cb[v0 + 3];

    if (tid < QT * FF)
        S.cat[tid >> 6][tid & 63] =
            x[(base + v0 + (tid >> 6)) * FF + (tid & 63)];
    {
        uint4* h4 = reinterpret_cast<uint4*>(&S.hist[0][0]);
        h4[tid]       = make_uint4(0u, 0u, 0u, 0u);
        h4[tid + TPB] = make_uint4(0u, 0u, 0u, 0u);
    }
    if (tid < QT) { S.cdef[tid] = 0; S.cbnd[tid] = 0; }
    __syncthreads();

    // ---- Pass 1: one coord load -> four distances; store 16-bit prefixes
    //      + four histogram bumps. Self d2 == 0 (bin 0); patched after. ----
#pragma unroll 2
    for (int i = tid; i < VV; i += TPB) {
        float4 cu = cb[i];
        float e0 = dist2(cq0, cu);
        float e1 = dist2(cq1, cu);
        float e2 = dist2(cq2, cu);
        float e3 = dist2(cq3, cu);
        unsigned u0 = __float_as_uint(e0);
        unsigned u1 = __float_as_uint(e1);
        unsigned u2 = __float_as_uint(e2);
        unsigned u3 = __float_as_uint(e3);
        S.pref[0][i] = (unsigned short)(u0 >> 16);
        S.pref[1][i] = (unsigned short)(u1 >> 16);
        S.pref[2][i] = (unsigned short)(u2 >> 16);
        S.pref[3][i] = (unsigned short)(u3 >> 16);
        atomicAdd(&S.hist[0][d2_key(u0)], 1u);
        atomicAdd(&S.hist[1][d2_key(u1)], 1u);
        atomicAdd(&S.hist[2][d2_key(u2)], 1u);
        atomicAdd(&S.hist[3][d2_key(u3)], 1u);
    }
    __syncthreads();
    if (tid < QT) {
        S.hist[tid][0]      -= 1u;              // remove self (d2=0 -> bin 0)
        S.hist[tid][NB - 1] += 1u;              // park self in top bin
        S.pref[tid][v0 + tid] = 0xFFFFu;        // sentinel: never gathered
    }
    __syncthreads();

    // ---- Parallel scan (1024 bins, 8/thread), four histograms at once ----
    {
        const uint4* hq = reinterpret_cast<const uint4*>(&S.hist[q][0]);
        uint4 a  = hq[2 * wt];
        uint4 c4 = hq[2 * wt + 1];
        unsigned h[8];
        h[0] = a.x;  h[1] = a.y;  h[2] = a.z;  h[3] = a.w;
        h[4] = c4.x; h[5] = c4.y; h[6] = c4.z; h[7] = c4.w;
        int lsum = 0;
#pragma unroll
        for (int j = 0; j < 8; ++j) lsum += (int)h[j];
        int incl = lsum;
#pragma unroll
        for (int o = 1; o < 32; o <<= 1) {
            int n = __shfl_up_sync(0xffffffffu, incl, o);
            if (lane >= o) incl += n;
        }
        if (lane == 31) S.wsc[q][wt >> 5] = incl;
        __syncthreads();
        int wprefix = 0;
        const int wid = wt >> 5;
        if (wid > 0) wprefix += S.wsc[q][0];
        if (wid > 1) wprefix += S.wsc[q][1];
        if (wid > 2) wprefix += S.wsc[q][2];
        int excl = wprefix + incl - lsum;       // count before bin wt*8
        if (excl < KN && excl + lsum >= KN) {
            int cum = excl;
#pragma unroll
            for (int j = 0; j < 8; ++j) {
                if (cum + (int)h[j] >= KN) {
                    S.bkey[q] = wt * 8 + j; S.cc[q] = cum; break;
                }
                cum += (int)h[j];
            }
        }
        __syncthreads();
    }
    const int bkey = S.bkey[q];
    const int c = S.cc[q];                      // definite count (< 39)
    const float4 cqm = (q == 0) ? cq0 : (q == 1) ? cq1 : (q == 2) ? cq2 : cq3;
    // 16-bit thresholds; bin bounds are multiples of 2^19 = 8*2^16 -> exact.
    const unsigned lo16 = (bkey == 0) ? 0u
                        : ((unsigned)(bkey + KBASE) << 3);
    const unsigned hi16 = (bkey == NB - 1) ? 0xFFFFu
                        : ((unsigned)(bkey + 1 + KBASE) << 3);

    // ---- Gather: sweep own prefix array (uint4 = 8 candidates/iter);
    //      recompute exact d2 only for hits (~42 per query). ----
    for (int it = 0; it < VV / 8 / 128; ++it) {
        int i8 = it * 128 + wt;
        uint4 a = reinterpret_cast<const uint4*>(&S.pref[q][0])[i8];
        int ib = i8 * 8;
#pragma unroll
        for (int e = 0; e < 8; ++e) {
            unsigned word = (e < 2) ? a.x : (e < 4) ? a.y : (e < 6) ? a.z : a.w;
            unsigned p16 = (e & 1) ? (word >> 16) : (word & 0xFFFFu);
            if (p16 < hi16) {
                int i = ib + e;
                float dv = dist2(cqm, cb[i]);
                if (p16 < lo16) {
                    int pos = atomicAdd(&S.cdef[q], 1);
                    S.nidx[q][pos] = i;
                    S.nd2[q][pos] = dv;
                } else {
                    int pos = atomicAdd(&S.cbnd[q], 1);
                    if (pos < BND_MAX)
                        S.bnd[q][pos] =
                            ((unsigned long long)__float_as_uint(dv) << 32)
                            | (unsigned)i;
                }
            }
        }
    }
    barq(q);

    const int m = S.cbnd[q];
    const int r = KN - c;                       // boundary picks needed (>=1)

    if (m <= 32) {
        // Common case: whole boundary list fits in warp 0 of the quarter.
        // r min-extractions with pure shfl butterflies; NO barriers inside.
        if (wt < 32) {
            unsigned long long lk = (lane < m) ? S.bnd[q][lane]
                                               : 0xFFFFFFFFFFFFFFFFULL;
            for (int j = 0; j < r; ++j) {
                unsigned long long w0 = lk;
#pragma unroll
                for (int o = 16; o > 0; o >>= 1)
                    w0 = ullmin2(w0, __shfl_xor_sync(0xffffffffu, w0, o));
                if (lk == w0) lk = 0xFFFFFFFFFFFFFFFFULL;  // consume winner
                if (lane == 0) {
                    S.nidx[q][c + j] = (int)(w0 & 0xFFFFFFFFULL);
                    S.nd2[q][c + j]  = __uint_as_float((unsigned)(w0 >> 32));
                }
            }
        }
        barq(q);
    } else if (m <= BND_MAX) {
        // Extract r smallest by (d2, idx) from the small boundary list.
        for (int j = 0; j < r; ++j) {
            unsigned long long lk = (wt < m) ? S.bnd[q][wt]
                                             : 0xFFFFFFFFFFFFFFFFULL;
#pragma unroll
            for (int o = 16; o > 0; o >>= 1) {
                unsigned long long oth = __shfl_down_sync(0xffffffffu, lk, o);
                lk = (oth < lk) ? oth : lk;
            }
            if (lane == 0) S.red[q][wt >> 5] = lk;
            barq(q);
            if (wt == 0) {
                unsigned long long w0 = S.red[q][0];
                if (S.red[q][1] < w0) w0 = S.red[q][1];
                if (S.red[q][2] < w0) w0 = S.red[q][2];
                if (S.red[q][3] < w0) w0 = S.red[q][3];
                S.win[q] = w0;
                S.nidx[q][c + j] = (int)(w0 & 0xFFFFFFFFULL);
                S.nd2[q][c + j]  = __uint_as_float((unsigned)(w0 >> 32));
            }
            barq(q);
            if (wt < m && S.bnd[q][wt] == S.win[q])
                S.bnd[q][wt] = 0xFFFFFFFFFFFFFFFFULL;
            barq(q);
        }
    } else {
        // Degenerate fallback (massive tie bin): exact extraction over
        // prefixes with recompute; consumed entries marked in pref.
        for (int j = 0; j < r; ++j) {
            unsigned long long lk = 0xFFFFFFFFFFFFFFFFULL;
            for (int i = wt; i < VV; i += 128) {
                unsigned p16 = S.pref[q][i];
                if (p16 >= lo16 && p16 < hi16) {
                    unsigned u = __float_as_uint(dist2(cqm, cb[i]));
                    unsigned long long key =
                        ((unsigned long long)u << 32) | (unsigned)i;
                    if (key < lk) lk = key;
                }
            }
#pragma unroll
            for (int o = 16; o > 0; o >>= 1) {
                unsigned long long oth = __shfl_down_sync(0xffffffffu, lk, o);
                lk = (oth < lk) ? oth : lk;
            }
            if (lane == 0) S.red[q][wt >> 5] = lk;
            barq(q);
            if (wt == 0) {
                unsigned long long w0 = S.red[q][0];
                if (S.red[q][1] < w0) w0 = S.red[q][1];
                if (S.red[q][2] < w0) w0 = S.red[q][2];
                if (S.red[q][3] < w0) w0 = S.red[q][3];
                int widx = (int)(w0 & 0xFFFFFFFFULL);
                S.nidx[q][c + j] = widx;
                S.nd2[q][c + j]  = __uint_as_float((unsigned)(w0 >> 32));
                S.pref[q][widx] = 0xFFFFu;      // consumed marker
            }
            barq(q);
        }
    }

    // ---- Weights ----
    if (wt < KN)
        S.nw[q][wt] = expf(-10.0f * fabsf(S.nd2[q][wt]));
    barq(q);

    // ---- Weighted aggregation: max + mean over 39 (per query quarter);
    //      unroll 8 to batch independent LDS+LDG chains (MLP). ----
    {
        const float* fb = g_feats + (size_t)base * FF;
        const int f = wt & 63;
        const int hj = wt >> 6;
        float mx = -CUDART_INF_F;
        float sm2 = 0.0f;
        if (hj) {
#pragma unroll 8
            for (int j = 20; j < KN; ++j) {
                float val = fb[S.nidx[q][j] * FF + f] * S.nw[q][j];
                mx = fmaxf(mx, val);
                sm2 += val;
            }
            S.mx2[q][f] = mx; S.sm2[q][f] = sm2;
        } else {
#pragma unroll 8
            for (int j = 0; j < 20; ++j) {
                float val = fb[S.nidx[q][j] * FF + f] * S.nw[q][j];
                mx = fmaxf(mx, val);
                sm2 += val;
            }
        }
        barq(q);
        if (!hj) {
            mx = fmaxf(mx, S.mx2[q][f]);
            sm2 += S.sm2[q][f];
            S.cat[q][FF + f]     = mx;
            S.cat[q][2 * FF + f] = sm2 * (1.0f / KN);
        }
    }
    __syncthreads();

    // ---- Output GEMM, Wo shared across all four queries ----
    {
        const int o = tid & 63;
        const int kseg = tid >> 6;              // 0..7
        const int k0 = kseg * 24;
        float a0 = 0.0f, a1 = 0.0f, a2 = 0.0f, a3 = 0.0f;
#pragma unroll
        for (int kk = 0; kk < 24; ++kk) {
            int k = k0 + kk;
            float w = Wo[k * OUTF + o];
            a0 = fmaf(S.cat[0][k], w, a0);
            a1 = fmaf(S.cat[1][k], w, a1);
            a2 = fmaf(S.cat[2][k], w, a2);
            a3 = fmaf(S.cat[3][k], w, a3);
        }
        S.part[kseg][0][o] = a0;
        S.part[kseg][1][o] = a1;
        S.part[kseg][2][o] = a2;
        S.part[kseg][3][o] = a3;
        __syncthreads();
        if (tid < QT * 64) {
            int qq = tid >> 6, oo = tid & 63;
            float acc = bo[oo];
#pragma unroll
            for (int s = 0; s < 8; ++s) acc += S.part[s][qq][oo];
            out[(base + v0 + qq) * OUTF + oo] = tanhf(acc);
        }
    }
}

// ---------------------------------------------------------------------------
extern "C" void kernel_launch(void* const* d_in, const int* in_sizes, int n_in,
                              void* d_out, int out_size)
{
    const float* x  = (const float*)d_in[0];
    const float* Wf = (const float*)d_in[1];
    const float* bf = (const float*)d_in[2];
    const float* Ws = (const float*)d_in[3];
    const float* bs = (const float*)d_in[4];
    const float* Wo = (const float*)d_in[5];
    const float* bo = (const float*)d_in[6];
    float* out = (float*)d_out;

    cudaFuncSetAttribute(grav_kernel,
                         cudaFuncAttributeMaxDynamicSharedMemorySize,
                         (int)sizeof(GravSmem));

    prep_kernel<<<BB * VV / 4, 256>>>(x, Wf, bf, Ws, bs);

    dim3 grid(VV / QT, BB);
    grav_kernel<<<grid, TPB, sizeof(GravSmem)>>>(x, Wo, bo, out);
}